// round 2
// baseline (speedup 1.0000x reference)
#include <cuda_runtime.h>
#include <cstdint>

#define N_NODES 100000
#define DEG 16
#define D 128
#define TILE_M 128
#define NTOT 256          // concatenated output cols (W1|W2)
#define APAD 132          // padded K stride -> conflict-free frag LDS
#define NTHREADS 256

// Scratch: Y1 = X@W1^T + (b1+b2),  Z = X@W2^T   (51.2 MB each)
__device__ float g_Y1[(size_t)N_NODES * D];
__device__ float g_Z [(size_t)N_NODES * D];

__device__ __forceinline__ unsigned tf32_of(float f) {
    unsigned r;
    asm("cvt.rna.tf32.f32 %0, %1;" : "=r"(r) : "f"(f));
    return r;
}

__device__ __forceinline__ void mma_tf32(float c[4], const unsigned a[4], const unsigned b[2]) {
    asm volatile(
        "mma.sync.aligned.m16n8k8.row.col.f32.tf32.tf32.f32 "
        "{%0,%1,%2,%3},{%4,%5,%6,%7},{%8,%9},{%0,%1,%2,%3};\n"
        : "+f"(c[0]), "+f"(c[1]), "+f"(c[2]), "+f"(c[3])
        : "r"(a[0]), "r"(a[1]), "r"(a[2]), "r"(a[3]),
          "r"(b[0]), "r"(b[1]));
}

extern __shared__ float smem_raw[];

// ---------------------------------------------------------------------------
// Kernel 1: dense GEMM  [Y1 | Z] = X @ [W1 | W2]^T  (+bias on Y1 half)
// Block: 256 thr, tile 128M x 256N x 128K. W staged in smem ONCE per block.
// ---------------------------------------------------------------------------
__global__ void __launch_bounds__(NTHREADS)
gconv_gemm_kernel(const float* __restrict__ x,
                  const float* __restrict__ W1,
                  const float* __restrict__ b1,
                  const float* __restrict__ W2,
                  const float* __restrict__ b2)
{
    float* As = smem_raw;                    // [TILE_M][APAD] tf32 bits
    float* Ws = smem_raw + TILE_M * APAD;    // [NTOT][APAD]   tf32 bits
    unsigned* Asu = reinterpret_cast<unsigned*>(As);
    unsigned* Wsu = reinterpret_cast<unsigned*>(Ws);

    const int tid  = threadIdx.x;
    const int warp = tid >> 5;
    const int lane = tid & 31;
    const int m0   = blockIdx.x * TILE_M;

    // Stage W (256x128) -> smem, tf32-converted. 8192 float4 / 256 thr = 32 it
    for (int i = tid; i < NTOT * (D / 4); i += NTHREADS) {
        const int row = i >> 5;
        const int c4  = (i & 31) * 4;
        const float* src = (row < D) ? (W1 + (size_t)row * D + c4)
                                     : (W2 + (size_t)(row - D) * D + c4);
        float4 v = __ldg(reinterpret_cast<const float4*>(src));
        uint4 tv = make_uint4(tf32_of(v.x), tf32_of(v.y), tf32_of(v.z), tf32_of(v.w));
        *reinterpret_cast<uint4*>(&Ws[row * APAD + c4]) = tv;
    }
    // Stage A tile (128x128) -> smem, tf32. 4096 float4 / 256 thr = 16 it
    for (int i = tid; i < TILE_M * (D / 4); i += NTHREADS) {
        const int row = i >> 5;
        const int c4  = (i & 31) * 4;
        const int node = m0 + row;
        float4 v = make_float4(0.f, 0.f, 0.f, 0.f);
        if (node < N_NODES)
            v = __ldg(reinterpret_cast<const float4*>(x + (size_t)node * D + c4));
        uint4 tv = make_uint4(tf32_of(v.x), tf32_of(v.y), tf32_of(v.z), tf32_of(v.w));
        *reinterpret_cast<uint4*>(&As[row * APAD + c4]) = tv;
    }
    __syncthreads();

    const int wm = warp >> 2;   // 0..1 -> 64 rows each
    const int wn = warp & 3;    // 0..3 -> 64 cols each
    const int g  = lane >> 2;
    const int t  = lane & 3;

    float c[4][8][4];
    #pragma unroll
    for (int mi = 0; mi < 4; mi++)
        #pragma unroll
        for (int ni = 0; ni < 8; ni++)
            #pragma unroll
            for (int r = 0; r < 4; r++) c[mi][ni][r] = 0.f;

    #pragma unroll
    for (int ks = 0; ks < 16; ks++) {
        const int k0 = ks * 8;
        unsigned a[4][4];
        #pragma unroll
        for (int mi = 0; mi < 4; mi++) {
            const int r0 = wm * 64 + mi * 16 + g;
            a[mi][0] = Asu[r0 * APAD + k0 + t];
            a[mi][1] = Asu[(r0 + 8) * APAD + k0 + t];
            a[mi][2] = Asu[r0 * APAD + k0 + 4 + t];
            a[mi][3] = Asu[(r0 + 8) * APAD + k0 + 4 + t];
        }
        unsigned b[8][2];
        #pragma unroll
        for (int ni = 0; ni < 8; ni++) {
            const int o = wn * 64 + ni * 8 + g;
            b[ni][0] = Wsu[o * APAD + k0 + t];
            b[ni][1] = Wsu[o * APAD + k0 + 4 + t];
        }
        #pragma unroll
        for (int mi = 0; mi < 4; mi++)
            #pragma unroll
            for (int ni = 0; ni < 8; ni++)
                mma_tf32(c[mi][ni], a[mi], b[ni]);
    }

    // Epilogue: wn<2 -> Y1 (+ bias sum), wn>=2 -> Z
    const bool isY = (wn < 2);
    float* dstBase = isY ? g_Y1 : g_Z;
    #pragma unroll
    for (int mi = 0; mi < 4; mi++) {
        const int node0 = m0 + wm * 64 + mi * 16 + g;
        const int node1 = node0 + 8;
        #pragma unroll
        for (int ni = 0; ni < 8; ni++) {
            const int colg = wn * 64 + ni * 8 + 2 * t;
            const int col  = isY ? colg : (colg - D);
            float bs0 = 0.f, bs1 = 0.f;
            if (isY) {
                bs0 = __ldg(b1 + col) + __ldg(b2 + col);
                bs1 = __ldg(b1 + col + 1) + __ldg(b2 + col + 1);
            }
            if (node0 < N_NODES) {
                float2 v0;
                v0.x = c[mi][ni][0] + bs0;
                v0.y = c[mi][ni][1] + bs1;
                *reinterpret_cast<float2*>(&dstBase[(size_t)node0 * D + col]) = v0;
            }
            if (node1 < N_NODES) {
                float2 v1;
                v1.x = c[mi][ni][2] + bs0;
                v1.y = c[mi][ni][3] + bs1;
                *reinterpret_cast<float2*>(&dstBase[(size_t)node1 * D + col]) = v1;
            }
        }
    }
}

// ---------------------------------------------------------------------------
// Kernel 2: pure gather.  out[n] = relu(Y1[n] + sum_j Z[nbr[n][j]])
// One warp per node, float4 per lane. No smem, full occupancy, L2-streaming.
// ---------------------------------------------------------------------------
__global__ void __launch_bounds__(NTHREADS)
gconv_gather_kernel(const int* __restrict__ nbr,
                    float* __restrict__ out)
{
    const int warp = threadIdx.x >> 5;
    const int lane = threadIdx.x & 31;
    const int node = blockIdx.x * (NTHREADS / 32) + warp;
    if (node >= N_NODES) return;

    int idx = 0;
    if (lane < DEG) idx = __ldg(nbr + (size_t)node * DEG + lane);

    const float4* Y4 = reinterpret_cast<const float4*>(g_Y1);
    const float4* Z4 = reinterpret_cast<const float4*>(g_Z);

    float4 acc = __ldg(Y4 + (size_t)node * 32 + lane);
    #pragma unroll
    for (int j = 0; j < DEG; j++) {
        const int nj = __shfl_sync(0xffffffffu, idx, j);
        float4 v = __ldg(Z4 + (size_t)nj * 32 + lane);
        acc.x += v.x; acc.y += v.y; acc.z += v.z; acc.w += v.w;
    }
    float4 r;
    r.x = fmaxf(acc.x, 0.f);
    r.y = fmaxf(acc.y, 0.f);
    r.z = fmaxf(acc.z, 0.f);
    r.w = fmaxf(acc.w, 0.f);
    *reinterpret_cast<float4*>(&out[(size_t)node * D + 4 * lane]) = r;
}

extern "C" void kernel_launch(void* const* d_in, const int* in_sizes, int n_in,
                              void* d_out, int out_size)
{
    const int*   nbr = (const int*)d_in[0];
    const float* x   = (const float*)d_in[1];
    const float* W1  = (const float*)d_in[2];
    const float* b1  = (const float*)d_in[3];
    const float* W2  = (const float*)d_in[4];
    const float* b2  = (const float*)d_in[5];
    float*       out = (float*)d_out;

    const int smem_bytes = (TILE_M * APAD + NTOT * APAD) * (int)sizeof(float); // 202,752 B
    cudaFuncSetAttribute(gconv_gemm_kernel,
                         cudaFuncAttributeMaxDynamicSharedMemorySize, smem_bytes);

    const int grid1 = (N_NODES + TILE_M - 1) / TILE_M;           // 782
    gconv_gemm_kernel<<<grid1, NTHREADS, smem_bytes>>>(x, W1, b1, W2, b2);

    const int grid2 = (N_NODES + (NTHREADS / 32) - 1) / (NTHREADS / 32); // 12500
    gconv_gather_kernel<<<grid2, NTHREADS>>>(nbr, out);
}

// round 3
// speedup vs baseline: 1.0099x; 1.0099x over previous
#include <cuda_runtime.h>
#include <cstdint>

#define N_NODES 100000
#define DEG 16
#define D 128
#define TILE_M 64
#define APAD 132          // stride mod 32 == 4 -> conflict-free frag LDS
#define NTHREADS 256

// Scratch: Y1 = X@W1^T + (b1+b2),  Z = X@W2^T   (51.2 MB each)
__device__ __align__(16) float g_Y1[(size_t)N_NODES * D];
__device__ __align__(16) float g_Z [(size_t)N_NODES * D];

__device__ __forceinline__ unsigned tf32_of(float f) {
    unsigned r;
    asm("cvt.rna.tf32.f32 %0, %1;" : "=r"(r) : "f"(f));
    return r;
}

__device__ __forceinline__ void mma_tf32(float c[4], const unsigned a[4], const unsigned b[2]) {
    asm volatile(
        "mma.sync.aligned.m16n8k8.row.col.f32.tf32.tf32.f32 "
        "{%0,%1,%2,%3},{%4,%5,%6,%7},{%8,%9},{%0,%1,%2,%3};\n"
        : "+f"(c[0]), "+f"(c[1]), "+f"(c[2]), "+f"(c[3])
        : "r"(a[0]), "r"(a[1]), "r"(a[2]), "r"(a[3]),
          "r"(b[0]), "r"(b[1]));
}

extern __shared__ float smem_raw[];

// ---------------------------------------------------------------------------
// Kernel 1: dense GEMM. blockIdx.y==0: Y1 = X@W1^T + (b1+b2); ==1: Z = X@W2^T
// Tile 64M x 128N x 128K, 256 thr, smem ~102KB -> 2 CTAs/SM (16 warps).
// ---------------------------------------------------------------------------
__global__ void __launch_bounds__(NTHREADS, 2)
gconv_gemm_kernel(const float* __restrict__ x,
                  const float* __restrict__ W1,
                  const float* __restrict__ b1,
                  const float* __restrict__ W2,
                  const float* __restrict__ b2)
{
    float* As = smem_raw;                      // [TILE_M][APAD] tf32 bits
    float* Ws = smem_raw + TILE_M * APAD;      // [D][APAD]      tf32 bits
    float* bias_s = Ws + D * APAD;             // [D]
    unsigned* Asu = reinterpret_cast<unsigned*>(As);
    unsigned* Wsu = reinterpret_cast<unsigned*>(Ws);

    const int tid  = threadIdx.x;
    const int warp = tid >> 5;
    const int lane = tid & 31;
    const int m0   = blockIdx.x * TILE_M;
    const bool isY = (blockIdx.y == 0);
    const float* W = isY ? W1 : W2;

    if (tid < D) bias_s[tid] = isY ? (__ldg(b1 + tid) + __ldg(b2 + tid)) : 0.f;

    // Stage W-half (128x128) -> smem tf32. 4096 float4 / 256 thr = 16 it.
    for (int i = tid; i < D * (D / 4); i += NTHREADS) {
        const int row = i >> 5;
        const int c4  = (i & 31) * 4;
        float4 v = __ldg(reinterpret_cast<const float4*>(W + (size_t)row * D + c4));
        uint4 tv = make_uint4(tf32_of(v.x), tf32_of(v.y), tf32_of(v.z), tf32_of(v.w));
        *reinterpret_cast<uint4*>(&Ws[row * APAD + c4]) = tv;
    }
    // Stage A tile (64x128) -> smem tf32. 2048 float4 / 256 thr = 8 it.
    for (int i = tid; i < TILE_M * (D / 4); i += NTHREADS) {
        const int row = i >> 5;
        const int c4  = (i & 31) * 4;
        const int node = m0 + row;
        float4 v = make_float4(0.f, 0.f, 0.f, 0.f);
        if (node < N_NODES)
            v = __ldg(reinterpret_cast<const float4*>(x + (size_t)node * D + c4));
        uint4 tv = make_uint4(tf32_of(v.x), tf32_of(v.y), tf32_of(v.z), tf32_of(v.w));
        *reinterpret_cast<uint4*>(&As[row * APAD + c4]) = tv;
    }
    __syncthreads();

    const int wm = warp >> 2;   // 0..1 -> 32 rows each
    const int wn = warp & 3;    // 0..3 -> 32 cols each
    const int g  = lane >> 2;
    const int t  = lane & 3;

    float c[2][4][4];
    #pragma unroll
    for (int mi = 0; mi < 2; mi++)
        #pragma unroll
        for (int ni = 0; ni < 4; ni++)
            #pragma unroll
            for (int r = 0; r < 4; r++) c[mi][ni][r] = 0.f;

    #pragma unroll
    for (int ks = 0; ks < 16; ks++) {
        const int k0 = ks * 8;
        unsigned a[2][4];
        #pragma unroll
        for (int mi = 0; mi < 2; mi++) {
            const int r0 = wm * 32 + mi * 16 + g;
            a[mi][0] = Asu[r0 * APAD + k0 + t];
            a[mi][1] = Asu[(r0 + 8) * APAD + k0 + t];
            a[mi][2] = Asu[r0 * APAD + k0 + 4 + t];
            a[mi][3] = Asu[(r0 + 8) * APAD + k0 + 4 + t];
        }
        unsigned b[4][2];
        #pragma unroll
        for (int ni = 0; ni < 4; ni++) {
            const int o = wn * 32 + ni * 8 + g;
            b[ni][0] = Wsu[o * APAD + k0 + t];
            b[ni][1] = Wsu[o * APAD + k0 + 4 + t];
        }
        #pragma unroll
        for (int mi = 0; mi < 2; mi++)
            #pragma unroll
            for (int ni = 0; ni < 4; ni++)
                mma_tf32(c[mi][ni], a[mi], b[ni]);
    }

    float* dstBase = isY ? g_Y1 : g_Z;
    #pragma unroll
    for (int mi = 0; mi < 2; mi++) {
        const int node0 = m0 + wm * 32 + mi * 16 + g;
        const int node1 = node0 + 8;
        #pragma unroll
        for (int ni = 0; ni < 4; ni++) {
            const int col = wn * 32 + ni * 8 + 2 * t;
            const float bs0 = bias_s[col];
            const float bs1 = bias_s[col + 1];
            if (node0 < N_NODES) {
                float2 v0;
                v0.x = c[mi][ni][0] + bs0;
                v0.y = c[mi][ni][1] + bs1;
                *reinterpret_cast<float2*>(&dstBase[(size_t)node0 * D + col]) = v0;
            }
            if (node1 < N_NODES) {
                float2 v1;
                v1.x = c[mi][ni][2] + bs0;
                v1.y = c[mi][ni][3] + bs1;
                *reinterpret_cast<float2*>(&dstBase[(size_t)node1 * D + col]) = v1;
            }
        }
    }
}

// ---------------------------------------------------------------------------
// Kernel 2: pure gather.  out[n] = relu(Y1[n] + sum_j Z[nbr[n][j]])
// One warp per node, float4 per lane. No smem, full occupancy, L2-streaming.
// ---------------------------------------------------------------------------
__global__ void __launch_bounds__(NTHREADS)
gconv_gather_kernel(const int* __restrict__ nbr,
                    float* __restrict__ out)
{
    const int warp = threadIdx.x >> 5;
    const int lane = threadIdx.x & 31;
    const int node = blockIdx.x * (NTHREADS / 32) + warp;
    if (node >= N_NODES) return;

    int idx = 0;
    if (lane < DEG) idx = __ldg(nbr + (size_t)node * DEG + lane);

    const float4* Y4 = reinterpret_cast<const float4*>(g_Y1);
    const float4* Z4 = reinterpret_cast<const float4*>(g_Z);

    float4 acc = __ldg(Y4 + (size_t)node * 32 + lane);
    #pragma unroll
    for (int j = 0; j < DEG; j++) {
        const int nj = __shfl_sync(0xffffffffu, idx, j);
        float4 v = __ldg(Z4 + (size_t)nj * 32 + lane);
        acc.x += v.x; acc.y += v.y; acc.z += v.z; acc.w += v.w;
    }
    float4 r;
    r.x = fmaxf(acc.x, 0.f);
    r.y = fmaxf(acc.y, 0.f);
    r.z = fmaxf(acc.z, 0.f);
    r.w = fmaxf(acc.w, 0.f);
    *reinterpret_cast<float4*>(&out[(size_t)node * D + 4 * lane]) = r;
}

extern "C" void kernel_launch(void* const* d_in, const int* in_sizes, int n_in,
                              void* d_out, int out_size)
{
    const int*   nbr = (const int*)d_in[0];
    const float* x   = (const float*)d_in[1];
    const float* W1  = (const float*)d_in[2];
    const float* b1  = (const float*)d_in[3];
    const float* W2  = (const float*)d_in[4];
    const float* b2  = (const float*)d_in[5];
    float*       out = (float*)d_out;

    const int smem_bytes = (TILE_M * APAD + D * APAD + D) * (int)sizeof(float); // 101,888 B
    cudaFuncSetAttribute(gconv_gemm_kernel,
                         cudaFuncAttributeMaxDynamicSharedMemorySize, smem_bytes);

    dim3 grid1((N_NODES + TILE_M - 1) / TILE_M, 2);   // 1563 x 2
    gconv_gemm_kernel<<<grid1, NTHREADS, smem_bytes>>>(x, W1, b1, W2, b2);

    const int grid2 = (N_NODES + (NTHREADS / 32) - 1) / (NTHREADS / 32); // 12500
    gconv_gather_kernel<<<grid2, NTHREADS>>>(nbr, out);
}

// round 5
// speedup vs baseline: 1.9777x; 1.9583x over previous
#include <cuda_runtime.h>
#include <cuda_fp16.h>
#include <cstdint>

#define N_NODES 100000
#define DEG 16
#define D 128
#define TILE_M 128
#define NTHREADS 256
#define STRH 136            // half-stride per row = 17 x 16B -> LDSM conflict-free

// fp16 shadows + scratch
__device__ __align__(16) __half g_xh [(size_t)N_NODES * D];
__device__ __align__(16) __half g_W1h[D * D];
__device__ __align__(16) __half g_W2h[D * D];
__device__ __align__(16) float  g_Y1 [(size_t)N_NODES * D];   // fp32, dense-read once
__device__ __align__(16) __half g_Zh [(size_t)N_NODES * D];   // fp16, gathered 16x

// smem layout (bytes)
#define SMEM_A    0
#define SMEM_B    (TILE_M * STRH * 2)          // 34816
#define SMEM_BIAS (SMEM_B + D * STRH * 2)      // 69632
#define SMEM_TOTAL (SMEM_BIAS + D * 4)         // 70144

__device__ __forceinline__ uint32_t smem_u32(const void* p) {
    uint32_t a;
    asm("{ .reg .u64 t; cvta.to.shared.u64 t, %1; cvt.u32.u64 %0, t; }" : "=r"(a) : "l"(p));
    return a;
}

__device__ __forceinline__ void ldsm_x4(uint32_t& r0, uint32_t& r1, uint32_t& r2, uint32_t& r3,
                                        uint32_t addr) {
    asm volatile("ldmatrix.sync.aligned.m8n8.x4.shared.b16 {%0,%1,%2,%3}, [%4];"
                 : "=r"(r0), "=r"(r1), "=r"(r2), "=r"(r3) : "r"(addr));
}

__device__ __forceinline__ void mma_f16(float c[4], const uint32_t a[4], const uint32_t b[2]) {
    asm volatile(
        "mma.sync.aligned.m16n8k16.row.col.f32.f16.f16.f32 "
        "{%0,%1,%2,%3},{%4,%5,%6,%7},{%8,%9},{%0,%1,%2,%3};\n"
        : "+f"(c[0]), "+f"(c[1]), "+f"(c[2]), "+f"(c[3])
        : "r"(a[0]), "r"(a[1]), "r"(a[2]), "r"(a[3]),
          "r"(b[0]), "r"(b[1]));
}

extern __shared__ char smem_raw[];

// ---------------------------------------------------------------------------
// Kernel 0: fp32 -> fp16 conversion of x, W1, W2
// ---------------------------------------------------------------------------
__global__ void __launch_bounds__(NTHREADS)
convert_kernel(const float* __restrict__ x,
               const float* __restrict__ W1,
               const float* __restrict__ W2)
{
    const int b = blockIdx.x;
    const float* src;
    __half* dst;
    size_t base;
    if (b < 12500)       { src = x;  dst = g_xh;  base = (size_t)b * NTHREADS; }
    else if (b < 12516)  { src = W1; dst = g_W1h; base = (size_t)(b - 12500) * NTHREADS; }
    else                 { src = W2; dst = g_W2h; base = (size_t)(b - 12516) * NTHREADS; }
    const size_t i = base + threadIdx.x;      // float4 index
    float4 v = __ldg(reinterpret_cast<const float4*>(src) + i);
    __half2 h0 = __floats2half2_rn(v.x, v.y);
    __half2 h1 = __floats2half2_rn(v.z, v.w);
    uint2 u;
    u.x = *reinterpret_cast<const unsigned*>(&h0);
    u.y = *reinterpret_cast<const unsigned*>(&h1);
    *(reinterpret_cast<uint2*>(dst) + i) = u;
}

// ---------------------------------------------------------------------------
// Kernel 1: fp16 GEMM.  y==0: Y1 = X@W1^T + (b1+b2) [fp32];  y==1: Zh = X@W2^T [fp16]
// Tile 128M x 128N x 128K, 8 warps, warp tile 64x32, m16n8k16, ldmatrix frags.
// ---------------------------------------------------------------------------
__global__ void __launch_bounds__(NTHREADS, 2)
gconv_gemm_h(const float* __restrict__ b1, const float* __restrict__ b2)
{
    const uint32_t sb = smem_u32(smem_raw);
    float* bias_s = reinterpret_cast<float*>(smem_raw + SMEM_BIAS);

    const int tid  = threadIdx.x;
    const int warp = tid >> 5;
    const int lane = tid & 31;
    const int m0   = blockIdx.x * TILE_M;
    const bool isY = (blockIdx.y == 0);
    const __half* Wh = isY ? g_W1h : g_W2h;

    if (tid < D) bias_s[tid] = isY ? (__ldg(b1 + tid) + __ldg(b2 + tid)) : 0.f;

    // Stage A (x tile, 128x128 half) and B (W, 128x128 half): uint4 = 8 halves
    const uint4* xh4 = reinterpret_cast<const uint4*>(g_xh);
    const uint4* wh4 = reinterpret_cast<const uint4*>(Wh);
    #pragma unroll
    for (int it = 0; it < 8; it++) {
        const int i   = it * NTHREADS + tid;     // 0..2047
        const int row = i >> 4;
        const int c8  = i & 15;
        const int node = m0 + row;
        uint4 va = make_uint4(0u, 0u, 0u, 0u);
        if (node < N_NODES) va = __ldg(xh4 + (size_t)node * 16 + c8);
        *reinterpret_cast<uint4*>(smem_raw + SMEM_A + (row * STRH + c8 * 8) * 2) = va;
        uint4 vb = __ldg(wh4 + (size_t)row * 16 + c8);
        *reinterpret_cast<uint4*>(smem_raw + SMEM_B + (row * STRH + c8 * 8) * 2) = vb;
    }
    __syncthreads();

    const int wm = warp >> 2;   // 0..1 -> 64 rows
    const int wn = warp & 3;    // 0..3 -> 32 cols
    const int g  = lane >> 2;
    const int t  = lane & 3;

    // ldmatrix per-lane base addresses
    const int arow = wm * 64 + (lane & 7) + ((lane >> 3) & 1) * 8;
    const int acol = ((lane >> 4) & 1) * 8;
    uint32_t aBase = sb + SMEM_A + (arow * STRH + acol) * 2;
    const int brow = wn * 32 + (lane & 7) + ((lane >> 4) & 1) * 8;
    const int bcol = ((lane >> 3) & 1) * 8;
    uint32_t bBase = sb + SMEM_B + (brow * STRH + bcol) * 2;

    float c[4][4][4];
    #pragma unroll
    for (int mi = 0; mi < 4; mi++)
        #pragma unroll
        for (int ni = 0; ni < 4; ni++)
            #pragma unroll
            for (int r = 0; r < 4; r++) c[mi][ni][r] = 0.f;

    #pragma unroll
    for (int ks = 0; ks < 8; ks++) {
        const uint32_t koff = ks * 32;     // 16 halves
        uint32_t a[4][4];
        #pragma unroll
        for (int mi = 0; mi < 4; mi++)
            ldsm_x4(a[mi][0], a[mi][1], a[mi][2], a[mi][3],
                    aBase + mi * (16 * STRH * 2) + koff);
        uint32_t b[4][2];
        #pragma unroll
        for (int p = 0; p < 2; p++) {
            uint32_t r0, r1, r2, r3;
            ldsm_x4(r0, r1, r2, r3, bBase + p * (16 * STRH * 2) + koff);
            b[p * 2 + 0][0] = r0; b[p * 2 + 0][1] = r1;
            b[p * 2 + 1][0] = r2; b[p * 2 + 1][1] = r3;
        }
        #pragma unroll
        for (int mi = 0; mi < 4; mi++)
            #pragma unroll
            for (int ni = 0; ni < 4; ni++)
                mma_f16(c[mi][ni], a[mi], b[ni]);
    }

    // Epilogue
    #pragma unroll
    for (int mi = 0; mi < 4; mi++) {
        const int node0 = m0 + wm * 64 + mi * 16 + g;
        const int node1 = node0 + 8;
        #pragma unroll
        for (int ni = 0; ni < 4; ni++) {
            const int col = wn * 32 + ni * 8 + 2 * t;
            if (isY) {
                const float bs0 = bias_s[col];
                const float bs1 = bias_s[col + 1];
                if (node0 < N_NODES) {
                    float2 v0 = make_float2(c[mi][ni][0] + bs0, c[mi][ni][1] + bs1);
                    *reinterpret_cast<float2*>(&g_Y1[(size_t)node0 * D + col]) = v0;
                }
                if (node1 < N_NODES) {
                    float2 v1 = make_float2(c[mi][ni][2] + bs0, c[mi][ni][3] + bs1);
                    *reinterpret_cast<float2*>(&g_Y1[(size_t)node1 * D + col]) = v1;
                }
            } else {
                if (node0 < N_NODES) {
                    __half2 h = __floats2half2_rn(c[mi][ni][0], c[mi][ni][1]);
                    *reinterpret_cast<__half2*>(&g_Zh[(size_t)node0 * D + col]) = h;
                }
                if (node1 < N_NODES) {
                    __half2 h = __floats2half2_rn(c[mi][ni][2], c[mi][ni][3]);
                    *reinterpret_cast<__half2*>(&g_Zh[(size_t)node1 * D + col]) = h;
                }
            }
        }
    }
}

// ---------------------------------------------------------------------------
// Kernel 2: gather.  out[n] = relu(Y1[n] + sum_j Zh[nbr[n][j]])
// One warp per node; per lane 4 output floats; Z rows read as uint2 (4 halves).
// ---------------------------------------------------------------------------
__global__ void __launch_bounds__(NTHREADS)
gconv_gather_kernel(const int* __restrict__ nbr,
                    float* __restrict__ out)
{
    const int warp = threadIdx.x >> 5;
    const int lane = threadIdx.x & 31;
    const int node = blockIdx.x * (NTHREADS / 32) + warp;
    if (node >= N_NODES) return;

    int idx = 0;
    if (lane < DEG) idx = __ldg(nbr + (size_t)node * DEG + lane);

    const float4* Y4 = reinterpret_cast<const float4*>(g_Y1);
    const uint2*  Z2 = reinterpret_cast<const uint2*>(g_Zh);

    float4 acc = __ldg(Y4 + (size_t)node * 32 + lane);
    #pragma unroll
    for (int j = 0; j < DEG; j++) {
        const int nj = __shfl_sync(0xffffffffu, idx, j);
        uint2 zv = __ldg(Z2 + (size_t)nj * 32 + lane);
        float2 f0 = __half22float2(*reinterpret_cast<const __half2*>(&zv.x));
        float2 f1 = __half22float2(*reinterpret_cast<const __half2*>(&zv.y));
        acc.x += f0.x; acc.y += f0.y; acc.z += f1.x; acc.w += f1.y;
    }
    float4 r;
    r.x = fmaxf(acc.x, 0.f);
    r.y = fmaxf(acc.y, 0.f);
    r.z = fmaxf(acc.z, 0.f);
    r.w = fmaxf(acc.w, 0.f);
    *reinterpret_cast<float4*>(&out[(size_t)node * D + 4 * lane]) = r;
}

extern "C" void kernel_launch(void* const* d_in, const int* in_sizes, int n_in,
                              void* d_out, int out_size)
{
    const int*   nbr = (const int*)d_in[0];
    const float* x   = (const float*)d_in[1];
    const float* W1  = (const float*)d_in[2];
    const float* b1  = (const float*)d_in[3];
    const float* W2  = (const float*)d_in[4];
    const float* b2  = (const float*)d_in[5];
    float*       out = (float*)d_out;

    cudaFuncSetAttribute(gconv_gemm_h,
                         cudaFuncAttributeMaxDynamicSharedMemorySize, SMEM_TOTAL);

    convert_kernel<<<12532, NTHREADS>>>(x, W1, W2);

    dim3 grid1((N_NODES + TILE_M - 1) / TILE_M, 2);   // 782 x 2
    gconv_gemm_h<<<grid1, NTHREADS, SMEM_TOTAL>>>(b1, b2);

    const int grid2 = (N_NODES + (NTHREADS / 32) - 1) / (NTHREADS / 32); // 12500
    gconv_gather_kernel<<<grid2, NTHREADS>>>(nbr, out);
}

// round 6
// speedup vs baseline: 2.2924x; 1.1591x over previous
#include <cuda_runtime.h>
#include <cuda_fp16.h>
#include <cstdint>

#define N_NODES 100000
#define DEG 16
#define D 128
#define TILE_M 128
#define NTHREADS 256
#define STRH 136            // half-stride per row = 17 x 16B -> LDSM conflict-free

// fp16 W shadows + fp16 scratch (Y1 incl. bias, Z)
__device__ __align__(16) __half g_W1h[D * D];
__device__ __align__(16) __half g_W2h[D * D];
__device__ __align__(16) __half g_Y1h[(size_t)N_NODES * D];
__device__ __align__(16) __half g_Zh [(size_t)N_NODES * D];

// smem layout (bytes): A[128][136]h, B[256][136]h (W1 rows 0-127, W2 rows 128-255), bias
#define SMEM_A    0
#define SMEM_B    (TILE_M * STRH * 2)               // 34816
#define SMEM_BIAS (SMEM_B + 2 * D * STRH * 2)       // 104448
#define SMEM_TOTAL (SMEM_BIAS + D * 4)              // 104960

__device__ __forceinline__ uint32_t smem_u32(const void* p) {
    uint32_t a;
    asm("{ .reg .u64 t; cvta.to.shared.u64 t, %1; cvt.u32.u64 %0, t; }" : "=r"(a) : "l"(p));
    return a;
}

__device__ __forceinline__ void ldsm_x4(uint32_t& r0, uint32_t& r1, uint32_t& r2, uint32_t& r3,
                                        uint32_t addr) {
    asm volatile("ldmatrix.sync.aligned.m8n8.x4.shared.b16 {%0,%1,%2,%3}, [%4];"
                 : "=r"(r0), "=r"(r1), "=r"(r2), "=r"(r3) : "r"(addr));
}

__device__ __forceinline__ void mma_f16(float c[4], const uint32_t a[4], const uint32_t b[2]) {
    asm volatile(
        "mma.sync.aligned.m16n8k16.row.col.f32.f16.f16.f32 "
        "{%0,%1,%2,%3},{%4,%5,%6,%7},{%8,%9},{%0,%1,%2,%3};\n"
        : "+f"(c[0]), "+f"(c[1]), "+f"(c[2]), "+f"(c[3])
        : "r"(a[0]), "r"(a[1]), "r"(a[2]), "r"(a[3]),
          "r"(b[0]), "r"(b[1]));
}

extern __shared__ char smem_raw[];

// ---------------------------------------------------------------------------
// Kernel 0: W1,W2 fp32 -> fp16 (tiny: 32 blocks)
// ---------------------------------------------------------------------------
__global__ void __launch_bounds__(NTHREADS)
convert_w_kernel(const float* __restrict__ W1, const float* __restrict__ W2)
{
    const int i = blockIdx.x * NTHREADS + threadIdx.x;   // float4 index, 8192 total
    const bool first = (i < 4096);
    const float* src = first ? W1 : W2;
    __half* dst = first ? g_W1h : g_W2h;
    const int j = first ? i : (i - 4096);
    float4 v = __ldg(reinterpret_cast<const float4*>(src) + j);
    __half2 h0 = __floats2half2_rn(v.x, v.y);
    __half2 h1 = __floats2half2_rn(v.z, v.w);
    uint2 u;
    u.x = *reinterpret_cast<const unsigned*>(&h0);
    u.y = *reinterpret_cast<const unsigned*>(&h1);
    *(reinterpret_cast<uint2*>(dst) + j) = u;
}

// ---------------------------------------------------------------------------
// Kernel 1: fused fp16 GEMM. A (x fp32 -> fp16) staged ONCE; two passes:
//   pass 0: Y1h = half(X@W1^T + (b1+b2));  pass 1: Zh = half(X@W2^T)
// Tile 128M x 128N x 128K per pass, 8 warps, warp tile 64x32, ldmatrix frags.
// ---------------------------------------------------------------------------
__global__ void __launch_bounds__(NTHREADS, 2)
gconv_gemm_h(const float* __restrict__ x,
             const float* __restrict__ b1, const float* __restrict__ b2)
{
    const uint32_t sb = smem_u32(smem_raw);
    float* bias_s = reinterpret_cast<float*>(smem_raw + SMEM_BIAS);

    const int tid  = threadIdx.x;
    const int warp = tid >> 5;
    const int lane = tid & 31;
    const int m0   = blockIdx.x * TILE_M;

    if (tid < D) bias_s[tid] = __ldg(b1 + tid) + __ldg(b2 + tid);

    // Stage B = [W1h; W2h] (256x128 half). 4096 uint4 / 256 thr = 16 it.
    const uint4* w1h4 = reinterpret_cast<const uint4*>(g_W1h);
    const uint4* w2h4 = reinterpret_cast<const uint4*>(g_W2h);
    #pragma unroll
    for (int it = 0; it < 16; it++) {
        const int i   = it * NTHREADS + tid;     // 0..4095
        const int row = i >> 4;                  // 0..255
        const int c8  = i & 15;
        uint4 vb = (row < D) ? __ldg(w1h4 + (size_t)row * 16 + c8)
                             : __ldg(w2h4 + (size_t)(row - D) * 16 + c8);
        *reinterpret_cast<uint4*>(smem_raw + SMEM_B + (row * STRH + c8 * 8) * 2) = vb;
    }
    // Stage A = x tile (128x128), fp32 global -> fp16 smem. 4096 float4 / 256 thr.
    #pragma unroll
    for (int it = 0; it < 16; it++) {
        const int i   = it * NTHREADS + tid;
        const int row = i >> 5;                  // 0..127
        const int c4  = (i & 31) * 4;            // float col
        const int node = m0 + row;
        float4 v = make_float4(0.f, 0.f, 0.f, 0.f);
        if (node < N_NODES)
            v = __ldg(reinterpret_cast<const float4*>(x + (size_t)node * D + c4));
        __half2 h0 = __floats2half2_rn(v.x, v.y);
        __half2 h1 = __floats2half2_rn(v.z, v.w);
        uint2 u;
        u.x = *reinterpret_cast<const unsigned*>(&h0);
        u.y = *reinterpret_cast<const unsigned*>(&h1);
        *reinterpret_cast<uint2*>(smem_raw + SMEM_A + (row * STRH + c4) * 2) = u;
    }
    __syncthreads();

    const int wm = warp >> 2;   // 0..1 -> 64 rows
    const int wn = warp & 3;    // 0..3 -> 32 cols
    const int g  = lane >> 2;
    const int t  = lane & 3;

    const int arow = wm * 64 + (lane & 7) + ((lane >> 3) & 1) * 8;
    const int acol = ((lane >> 4) & 1) * 8;
    const uint32_t aBase = sb + SMEM_A + (arow * STRH + acol) * 2;
    const int brow = wn * 32 + (lane & 7) + ((lane >> 4) & 1) * 8;
    const int bcol = ((lane >> 3) & 1) * 8;
    const uint32_t bBase0 = sb + SMEM_B + (brow * STRH + bcol) * 2;

    #pragma unroll
    for (int pass = 0; pass < 2; pass++) {
        const uint32_t bBase = bBase0 + (uint32_t)pass * (D * STRH * 2);

        float c[4][4][4];
        #pragma unroll
        for (int mi = 0; mi < 4; mi++)
            #pragma unroll
            for (int ni = 0; ni < 4; ni++)
                #pragma unroll
                for (int r = 0; r < 4; r++) c[mi][ni][r] = 0.f;

        #pragma unroll
        for (int ks = 0; ks < 8; ks++) {
            const uint32_t koff = ks * 32;     // 16 halves
            uint32_t a[4][4];
            #pragma unroll
            for (int mi = 0; mi < 4; mi++)
                ldsm_x4(a[mi][0], a[mi][1], a[mi][2], a[mi][3],
                        aBase + mi * (16 * STRH * 2) + koff);
            uint32_t b[4][2];
            #pragma unroll
            for (int p = 0; p < 2; p++) {
                uint32_t r0, r1, r2, r3;
                ldsm_x4(r0, r1, r2, r3, bBase + p * (16 * STRH * 2) + koff);
                b[p * 2 + 0][0] = r0; b[p * 2 + 0][1] = r1;
                b[p * 2 + 1][0] = r2; b[p * 2 + 1][1] = r3;
            }
            #pragma unroll
            for (int mi = 0; mi < 4; mi++)
                #pragma unroll
                for (int ni = 0; ni < 4; ni++)
                    mma_f16(c[mi][ni], a[mi], b[ni]);
        }

        __half* dst = (pass == 0) ? g_Y1h : g_Zh;
        const bool addBias = (pass == 0);
        #pragma unroll
        for (int mi = 0; mi < 4; mi++) {
            const int node0 = m0 + wm * 64 + mi * 16 + g;
            const int node1 = node0 + 8;
            #pragma unroll
            for (int ni = 0; ni < 4; ni++) {
                const int col = wn * 32 + ni * 8 + 2 * t;
                const float bs0 = addBias ? bias_s[col] : 0.f;
                const float bs1 = addBias ? bias_s[col + 1] : 0.f;
                if (node0 < N_NODES) {
                    __half2 h = __floats2half2_rn(c[mi][ni][0] + bs0, c[mi][ni][1] + bs1);
                    *reinterpret_cast<__half2*>(&dst[(size_t)node0 * D + col]) = h;
                }
                if (node1 < N_NODES) {
                    __half2 h = __floats2half2_rn(c[mi][ni][2] + bs0, c[mi][ni][3] + bs1);
                    *reinterpret_cast<__half2*>(&dst[(size_t)node1 * D + col]) = h;
                }
            }
        }
    }
}

// ---------------------------------------------------------------------------
// Kernel 2: gather.  out[n] = relu(Y1h[n] + sum_j Zh[nbr[n][j]])
// One warp per node; per lane 4 output floats; rows read as uint2 (4 halves).
// ---------------------------------------------------------------------------
__global__ void __launch_bounds__(NTHREADS)
gconv_gather_kernel(const int* __restrict__ nbr,
                    float* __restrict__ out)
{
    const int warp = threadIdx.x >> 5;
    const int lane = threadIdx.x & 31;
    const int node = blockIdx.x * (NTHREADS / 32) + warp;
    if (node >= N_NODES) return;

    int idx = 0;
    if (lane < DEG) idx = __ldg(nbr + (size_t)node * DEG + lane);

    const uint2* Y2 = reinterpret_cast<const uint2*>(g_Y1h);
    const uint2* Z2 = reinterpret_cast<const uint2*>(g_Zh);

    uint2 yv = __ldg(Y2 + (size_t)node * 32 + lane);
    float2 a0 = __half22float2(*reinterpret_cast<const __half2*>(&yv.x));
    float2 a1 = __half22float2(*reinterpret_cast<const __half2*>(&yv.y));
    float4 acc = make_float4(a0.x, a0.y, a1.x, a1.y);

    #pragma unroll
    for (int j = 0; j < DEG; j++) {
        const int nj = __shfl_sync(0xffffffffu, idx, j);
        uint2 zv = __ldg(Z2 + (size_t)nj * 32 + lane);
        float2 f0 = __half22float2(*reinterpret_cast<const __half2*>(&zv.x));
        float2 f1 = __half22float2(*reinterpret_cast<const __half2*>(&zv.y));
        acc.x += f0.x; acc.y += f0.y; acc.z += f1.x; acc.w += f1.y;
    }
    float4 r;
    r.x = fmaxf(acc.x, 0.f);
    r.y = fmaxf(acc.y, 0.f);
    r.z = fmaxf(acc.z, 0.f);
    r.w = fmaxf(acc.w, 0.f);
    *reinterpret_cast<float4*>(&out[(size_t)node * D + 4 * lane]) = r;
}

extern "C" void kernel_launch(void* const* d_in, const int* in_sizes, int n_in,
                              void* d_out, int out_size)
{
    const int*   nbr = (const int*)d_in[0];
    const float* x   = (const float*)d_in[1];
    const float* W1  = (const float*)d_in[2];
    const float* b1  = (const float*)d_in[3];
    const float* W2  = (const float*)d_in[4];
    const float* b2  = (const float*)d_in[5];
    float*       out = (float*)d_out;

    cudaFuncSetAttribute(gconv_gemm_h,
                         cudaFuncAttributeMaxDynamicSharedMemorySize, SMEM_TOTAL);

    convert_w_kernel<<<32, NTHREADS>>>(W1, W2);

    const int grid1 = (N_NODES + TILE_M - 1) / TILE_M;   // 782
    gconv_gemm_h<<<grid1, NTHREADS, SMEM_TOTAL>>>(x, b1, b2);

    const int grid2 = (N_NODES + (NTHREADS / 32) - 1) / (NTHREADS / 32); // 12500
    gconv_gather_kernel<<<grid2, NTHREADS>>>(nbr, out);
}